// round 2
// baseline (speedup 1.0000x reference)
#include <cuda_runtime.h>
#include <math.h>

#define B_ 4
#define N_ 1024
#define D_ 768
#define H_ 12
#define HD_ 64
#define ND3_ 2304

// Scratch (device globals — no allocation allowed)
__device__ float g_q[B_ * H_ * N_ * HD_];
__device__ float g_k[B_ * H_ * N_ * HD_];
__device__ float g_v[B_ * H_ * N_ * HD_];
__device__ float g_ctx[B_ * N_ * D_];

// ---------------------------------------------------------------------------
// Kernel 1: QKV GEMM.  C[m,n] = sum_k X[m,k] * W[k,n],  M=4096, N=2304, K=768.
// Epilogue scatters into g_q/g_k/g_v with layout [B,H,N,hd].
// 64x64 block tile, BK=16, 256 threads, 4x4 micro-tile, register prefetch.
// ---------------------------------------------------------------------------
__global__ __launch_bounds__(256) void qkv_gemm_kernel(
    const float* __restrict__ X, const float* __restrict__ W) {
    __shared__ float As[16][68];  // transposed: As[k][m]
    __shared__ float Bs[16][68];  // Bs[k][n]

    const int m0 = blockIdx.y * 64;
    const int n0 = blockIdx.x * 64;
    const int tid = threadIdx.x;
    const int ty = tid >> 4, tx = tid & 15;

    const int lrow = tid >> 2, lkq = tid & 3;   // A loader: row, k-quad
    const int lkr = tid >> 4, lnc = tid & 15;   // B loader: k-row, n-quad

    const float* xp = X + (size_t)(m0 + lrow) * D_ + lkq * 4;
    const float* wp = W + (size_t)lkr * ND3_ + n0 + lnc * 4;

    float4 pa = *(const float4*)xp;
    float4 pb = *(const float4*)wp;

    float acc[4][4];
#pragma unroll
    for (int i = 0; i < 4; i++)
#pragma unroll
        for (int j = 0; j < 4; j++) acc[i][j] = 0.0f;

    for (int kt = 0; kt < 48; ++kt) {
        As[lkq * 4 + 0][lrow] = pa.x;
        As[lkq * 4 + 1][lrow] = pa.y;
        As[lkq * 4 + 2][lrow] = pa.z;
        As[lkq * 4 + 3][lrow] = pa.w;
        *(float4*)&Bs[lkr][lnc * 4] = pb;
        __syncthreads();
        if (kt < 47) {
            pa = *(const float4*)(xp + (kt + 1) * 16);
            pb = *(const float4*)(wp + (size_t)(kt + 1) * 16 * ND3_);
        }
#pragma unroll
        for (int k = 0; k < 16; ++k) {
            float4 a4 = *(const float4*)&As[k][ty * 4];
            float4 b4 = *(const float4*)&Bs[k][tx * 4];
            acc[0][0] += a4.x * b4.x; acc[0][1] += a4.x * b4.y;
            acc[0][2] += a4.x * b4.z; acc[0][3] += a4.x * b4.w;
            acc[1][0] += a4.y * b4.x; acc[1][1] += a4.y * b4.y;
            acc[1][2] += a4.y * b4.z; acc[1][3] += a4.y * b4.w;
            acc[2][0] += a4.z * b4.x; acc[2][1] += a4.z * b4.y;
            acc[2][2] += a4.z * b4.z; acc[2][3] += a4.z * b4.w;
            acc[3][0] += a4.w * b4.x; acc[3][1] += a4.w * b4.y;
            acc[3][2] += a4.w * b4.z; acc[3][3] += a4.w * b4.w;
        }
        __syncthreads();
    }

    // Scatter: n-tile (64 wide) covers exactly one (which, head) pair.
    const int which = n0 / D_;               // 0=q,1=k,2=v
    const int h = (n0 - which * D_) >> 6;    // head
    float* dst = (which == 0) ? g_q : (which == 1) ? g_k : g_v;
#pragma unroll
    for (int i = 0; i < 4; ++i) {
        int m = m0 + ty * 4 + i;
        int b = m >> 10, r = m & 1023;
        float4 o = make_float4(acc[i][0], acc[i][1], acc[i][2], acc[i][3]);
        *(float4*)&dst[(((size_t)(b * H_ + h) * N_ + r) << 6) + tx * 4] = o;
    }
}

// ---------------------------------------------------------------------------
// Kernel 2: flash attention with fused bucketed rel-pos bias + elevation bias.
// Grid: (16 i-tiles, H, B), 256 threads. Dynamic smem.
// ---------------------------------------------------------------------------
#define ATTN_SMEM_FLOATS (3 * 64 * 68 + 1024 + 256 + 64 + 64 + 64)
#define ATTN_SMEM_BYTES (ATTN_SMEM_FLOATS * 4)

__global__ __launch_bounds__(256) void attn_kernel(
    const float* __restrict__ coords, const float* __restrict__ elev,
    const float* __restrict__ bias_table, const float* __restrict__ alphap) {
    extern __shared__ float smf[];
    float(*qs)[68] = (float(*)[68])smf;                  // [64][68] q natural
    float(*kps)[68] = (float(*)[68])(smf + 64 * 68);     // K transposed / P
    float(*vs)[68] = (float(*)[68])(smf + 2 * 64 * 68);  // V natural
    float* tbl = smf + 3 * 64 * 68;                      // per-head bias slice [1024]
    int* lut = (int*)(tbl + 1024);                       // bucket LUT [255]
    int* cjx = lut + 256;
    int* cjy = cjx + 64;
    float* ejs = (float*)(cjy + 64);

    const int i0 = blockIdx.x * 64;
    const int h = blockIdx.y;
    const int b = blockIdx.z;
    const int tid = threadIdx.x;
    const int ty = tid >> 4, tx = tid & 15;

    // per-head bias table slice
    for (int idx = tid; idx < 1024; idx += 256) tbl[idx] = bias_table[idx * H_ + h];

    // bucket LUT: rel in [-127,127]. Double-precision log matches XLA fp32
    // truncation (boundaries n=16/32/64 are exactly integral in both).
    if (tid < 255) {
        int rel = tid - 127;
        int ret = (rel > 0) ? 16 : 0;
        int n = (rel < 0) ? -rel : rel;
        int bb;
        if (n < 8) bb = n;
        else {
            int vi = (int)(log((double)n * 0.125) / log(16.0) * 8.0 + 1e-9);
            bb = 8 + vi;
            if (bb > 15) bb = 15;
        }
        lut[tid] = ret + bb;
    }

    // q tile
    const float* qbase = g_q + (((size_t)(b * H_ + h) * N_ + i0) << 6);
#pragma unroll
    for (int p = 0; p < 4; ++p) {
        int idx = tid + p * 256;
        int r = idx >> 4, dq = idx & 15;
        *(float4*)&qs[r][dq * 4] = *(const float4*)(qbase + r * 64 + dq * 4);
    }

    // per-row registers
    int cix[4], ciy[4];
    float eir[4];
#pragma unroll
    for (int i = 0; i < 4; ++i) {
        int g = b * N_ + i0 + ty * 4 + i;
        cix[i] = (int)(coords[g * 2 + 0] * 128.0f);
        ciy[i] = (int)(coords[g * 2 + 1] * 128.0f);
        eir[i] = elev[g] * (1.0f / 1000.0f);
    }
    const float alpha = *alphap;

    float oacc[4][4];
    float mrow[4], lrow[4];
#pragma unroll
    for (int i = 0; i < 4; ++i) {
        mrow[i] = -1e30f;
        lrow[i] = 0.0f;
#pragma unroll
        for (int j = 0; j < 4; ++j) oacc[i][j] = 0.0f;
    }

    const float* kbase0 = g_k + (((size_t)(b * H_ + h) * N_) << 6);
    const float* vbase0 = g_v + (((size_t)(b * H_ + h) * N_) << 6);

    for (int jt = 0; jt < 16; ++jt) {
        const int j0 = jt * 64;
        __syncthreads();  // protect kps/vs from previous iteration's readers
        const float* kbase = kbase0 + ((size_t)j0 << 6);
        const float* vbase = vbase0 + ((size_t)j0 << 6);
#pragma unroll
        for (int p = 0; p < 4; ++p) {
            int idx = tid + p * 256;
            int r = idx >> 4, dq = idx & 15;
            float4 kv = *(const float4*)(kbase + r * 64 + dq * 4);
            kps[dq * 4 + 0][r] = kv.x;
            kps[dq * 4 + 1][r] = kv.y;
            kps[dq * 4 + 2][r] = kv.z;
            kps[dq * 4 + 3][r] = kv.w;
            *(float4*)&vs[r][dq * 4] = *(const float4*)(vbase + r * 64 + dq * 4);
        }
        if (tid < 64) {
            int g = b * N_ + j0 + tid;
            cjx[tid] = (int)(coords[g * 2 + 0] * 128.0f);
            cjy[tid] = (int)(coords[g * 2 + 1] * 128.0f);
            ejs[tid] = elev[g] * (1.0f / 1000.0f);
        }
        __syncthreads();

        // S = Q K^T
        float s[4][4];
#pragma unroll
        for (int i = 0; i < 4; i++)
#pragma unroll
            for (int j = 0; j < 4; j++) s[i][j] = 0.0f;
#pragma unroll 16
        for (int d = 0; d < 64; ++d) {
            float4 b4 = *(const float4*)&kps[d][tx * 4];
#pragma unroll
            for (int i = 0; i < 4; ++i) {
                float a = qs[ty * 4 + i][d];
                s[i][0] += a * b4.x;
                s[i][1] += a * b4.y;
                s[i][2] += a * b4.z;
                s[i][3] += a * b4.w;
            }
        }

        // biases
#pragma unroll
        for (int i = 0; i < 4; ++i) {
#pragma unroll
            for (int j = 0; j < 4; ++j) {
                int jj = tx * 4 + j;
                float sc = s[i][j] * 0.125f;
                int bx = lut[cix[i] - cjx[jj] + 127];
                int by = lut[ciy[i] - cjy[jj] + 127];
                sc += tbl[(bx << 5) + by];
                float ed = ejs[jj] - eir[i];
                float eb = -alpha * fmaxf(ed, 0.0f);
                sc += fminf(fmaxf(eb, -10.0f), 0.0f);
                s[i][j] = sc;
            }
        }

        // online softmax (row groups = 16 lanes sharing ty)
#pragma unroll
        for (int i = 0; i < 4; ++i) {
            float tm = fmaxf(fmaxf(s[i][0], s[i][1]), fmaxf(s[i][2], s[i][3]));
            tm = fmaxf(tm, __shfl_xor_sync(0xffffffff, tm, 1));
            tm = fmaxf(tm, __shfl_xor_sync(0xffffffff, tm, 2));
            tm = fmaxf(tm, __shfl_xor_sync(0xffffffff, tm, 4));
            tm = fmaxf(tm, __shfl_xor_sync(0xffffffff, tm, 8));
            float mnew = fmaxf(mrow[i], tm);
            float corr = __expf(mrow[i] - mnew);
            mrow[i] = mnew;
            float psum = 0.0f;
#pragma unroll
            for (int j = 0; j < 4; ++j) {
                float pv = __expf(s[i][j] - mnew);
                s[i][j] = pv;
                psum += pv;
            }
            lrow[i] = lrow[i] * corr + psum;
            oacc[i][0] *= corr;
            oacc[i][1] *= corr;
            oacc[i][2] *= corr;
            oacc[i][3] *= corr;
        }

        __syncthreads();  // everyone done reading kps (K) before P overwrite
#pragma unroll
        for (int i = 0; i < 4; ++i)
            *(float4*)&kps[ty * 4 + i][tx * 4] =
                make_float4(s[i][0], s[i][1], s[i][2], s[i][3]);
        __syncthreads();

        // O += P V
#pragma unroll 16
        for (int jj = 0; jj < 64; ++jj) {
            float4 v4 = *(const float4*)&vs[jj][tx * 4];
#pragma unroll
            for (int i = 0; i < 4; ++i) {
                float pv = kps[ty * 4 + i][jj];
                oacc[i][0] += pv * v4.x;
                oacc[i][1] += pv * v4.y;
                oacc[i][2] += pv * v4.z;
                oacc[i][3] += pv * v4.w;
            }
        }
    }

    // finalize
#pragma unroll
    for (int i = 0; i < 4; ++i) {
        float l = lrow[i];
        l += __shfl_xor_sync(0xffffffff, l, 1);
        l += __shfl_xor_sync(0xffffffff, l, 2);
        l += __shfl_xor_sync(0xffffffff, l, 4);
        l += __shfl_xor_sync(0xffffffff, l, 8);
        float inv = 1.0f / l;
        int row = i0 + ty * 4 + i;
        float4 o = make_float4(oacc[i][0] * inv, oacc[i][1] * inv,
                               oacc[i][2] * inv, oacc[i][3] * inv);
        *(float4*)&g_ctx[((size_t)(b * N_ + row)) * D_ + h * 64 + tx * 4] = o;
    }
}

// ---------------------------------------------------------------------------
// Kernel 3: output projection.  out = ctx @ W_proj + b_proj.  M=4096,N=768,K=768
// ---------------------------------------------------------------------------
__global__ __launch_bounds__(256) void proj_gemm_kernel(
    const float* __restrict__ W, const float* __restrict__ bias,
    float* __restrict__ out) {
    __shared__ float As[16][68];
    __shared__ float Bs[16][68];

    const int m0 = blockIdx.y * 64;
    const int n0 = blockIdx.x * 64;
    const int tid = threadIdx.x;
    const int ty = tid >> 4, tx = tid & 15;

    const int lrow = tid >> 2, lkq = tid & 3;
    const int lkr = tid >> 4, lnc = tid & 15;

    const float* xp = g_ctx + (size_t)(m0 + lrow) * D_ + lkq * 4;
    const float* wp = W + (size_t)lkr * D_ + n0 + lnc * 4;

    float4 pa = *(const float4*)xp;
    float4 pb = *(const float4*)wp;

    float acc[4][4];
#pragma unroll
    for (int i = 0; i < 4; i++)
#pragma unroll
        for (int j = 0; j < 4; j++) acc[i][j] = 0.0f;

    for (int kt = 0; kt < 48; ++kt) {
        As[lkq * 4 + 0][lrow] = pa.x;
        As[lkq * 4 + 1][lrow] = pa.y;
        As[lkq * 4 + 2][lrow] = pa.z;
        As[lkq * 4 + 3][lrow] = pa.w;
        *(float4*)&Bs[lkr][lnc * 4] = pb;
        __syncthreads();
        if (kt < 47) {
            pa = *(const float4*)(xp + (kt + 1) * 16);
            pb = *(const float4*)(wp + (size_t)(kt + 1) * 16 * D_);
        }
#pragma unroll
        for (int k = 0; k < 16; ++k) {
            float4 a4 = *(const float4*)&As[k][ty * 4];
            float4 b4 = *(const float4*)&Bs[k][tx * 4];
            acc[0][0] += a4.x * b4.x; acc[0][1] += a4.x * b4.y;
            acc[0][2] += a4.x * b4.z; acc[0][3] += a4.x * b4.w;
            acc[1][0] += a4.y * b4.x; acc[1][1] += a4.y * b4.y;
            acc[1][2] += a4.y * b4.z; acc[1][3] += a4.y * b4.w;
            acc[2][0] += a4.z * b4.x; acc[2][1] += a4.z * b4.y;
            acc[2][2] += a4.z * b4.z; acc[2][3] += a4.z * b4.w;
            acc[3][0] += a4.w * b4.x; acc[3][1] += a4.w * b4.y;
            acc[3][2] += a4.w * b4.z; acc[3][3] += a4.w * b4.w;
        }
        __syncthreads();
    }

    float4 bb = *(const float4*)&bias[n0 + tx * 4];
#pragma unroll
    for (int i = 0; i < 4; ++i) {
        int m = m0 + ty * 4 + i;
        float4 o = make_float4(acc[i][0] + bb.x, acc[i][1] + bb.y,
                               acc[i][2] + bb.z, acc[i][3] + bb.w);
        *(float4*)&out[(size_t)m * D_ + n0 + tx * 4] = o;
    }
}

// ---------------------------------------------------------------------------
extern "C" void kernel_launch(void* const* d_in, const int* in_sizes, int n_in,
                              void* d_out, int out_size) {
    const float* x = (const float*)d_in[0];
    const float* coords = (const float*)d_in[1];
    const float* elev = (const float*)d_in[2];
    const float* W_qkv = (const float*)d_in[3];
    const float* W_proj = (const float*)d_in[4];
    const float* b_proj = (const float*)d_in[5];
    const float* bias_table = (const float*)d_in[6];
    const float* alpha = (const float*)d_in[7];
    float* out = (float*)d_out;

    cudaFuncSetAttribute(attn_kernel, cudaFuncAttributeMaxDynamicSharedMemorySize,
                         ATTN_SMEM_BYTES);

    qkv_gemm_kernel<<<dim3(ND3_ / 64, (B_ * N_) / 64), 256>>>(x, W_qkv);
    attn_kernel<<<dim3(N_ / 64, H_, B_), 256, ATTN_SMEM_BYTES>>>(coords, elev,
                                                                 bias_table, alpha);
    proj_gemm_kernel<<<dim3(D_ / 64, (B_ * N_) / 64), 256>>>(W_proj, b_proj, out);
}

// round 3
// speedup vs baseline: 1.2264x; 1.2264x over previous
#include <cuda_runtime.h>

#define B_ 4
#define N_ 1024
#define D_ 768
#define H_ 12
#define ND3_ 2304
typedef unsigned long long u64t;

__device__ float g_q[B_ * H_ * N_ * 64];
__device__ float g_k[B_ * H_ * N_ * 64];
__device__ float g_v[B_ * H_ * N_ * 64];
__device__ float g_ctx[B_ * N_ * D_];
__device__ unsigned short g_bidx[(size_t)B_ * N_ * N_];

__device__ __forceinline__ void ffma2(u64t& d, u64t a, u64t b) {
    asm("fma.rn.f32x2 %0, %1, %2, %0;" : "+l"(d) : "l"(a), "l"(b));
}
__device__ __forceinline__ u64t dup2(float x) {
    u64t r;
    asm("mov.b64 %0, {%1, %1};" : "=l"(r) : "f"(x));
    return r;
}

// ---------------- GEMM 128x128x16, 256 thr, 8x8 micro, f32x2 ----------------
template <bool IS_QKV>
__global__ __launch_bounds__(256, 2) void gemm128(const float* __restrict__ Xin,
                                                  const float* __restrict__ W,
                                                  const float* __restrict__ bias,
                                                  float* __restrict__ out) {
    constexpr int LDW = IS_QKV ? ND3_ : D_;
    __shared__ float As[16][132];
    __shared__ float Bs[16][132];
    const float* X = IS_QKV ? Xin : (const float*)g_ctx;

    const int m0 = blockIdx.y * 128, n0 = blockIdx.x * 128;
    const int tid = threadIdx.x;
    const int tx = tid & 15, ty = tid >> 4;
    const int arow = tid & 127, akb = (tid >> 7) * 8;
    const int bkr = tid >> 4, bc = (tid & 15) * 8;

    const float* xp = X + (size_t)(m0 + arow) * D_ + akb;
    const float* wp = W + (size_t)bkr * LDW + n0 + bc;
    float4 pa0 = *(const float4*)xp, pa1 = *(const float4*)(xp + 4);
    float4 pb0 = *(const float4*)wp, pb1 = *(const float4*)(wp + 4);

    u64t acc[4][8];
#pragma unroll
    for (int i = 0; i < 4; i++)
#pragma unroll
        for (int j = 0; j < 8; j++) acc[i][j] = 0ULL;

    for (int kt = 0; kt < 48; ++kt) {
        As[akb + 0][arow] = pa0.x; As[akb + 1][arow] = pa0.y;
        As[akb + 2][arow] = pa0.z; As[akb + 3][arow] = pa0.w;
        As[akb + 4][arow] = pa1.x; As[akb + 5][arow] = pa1.y;
        As[akb + 6][arow] = pa1.z; As[akb + 7][arow] = pa1.w;
        *(float4*)&Bs[bkr][bc] = pb0;
        *(float4*)&Bs[bkr][bc + 4] = pb1;
        __syncthreads();
        if (kt < 47) {
            const float* xn = xp + (kt + 1) * 16;
            pa0 = *(const float4*)xn; pa1 = *(const float4*)(xn + 4);
            const float* wn = wp + (size_t)(kt + 1) * 16 * LDW;
            pb0 = *(const float4*)wn; pb1 = *(const float4*)(wn + 4);
        }
#pragma unroll
        for (int k = 0; k < 16; ++k) {
            ulonglong2 a0 = *(const ulonglong2*)&As[k][ty * 8];
            ulonglong2 a1 = *(const ulonglong2*)&As[k][ty * 8 + 4];
            float4 b0 = *(const float4*)&Bs[k][tx * 4];
            float4 b1 = *(const float4*)&Bs[k][64 + tx * 4];
            u64t ap[4] = {a0.x, a0.y, a1.x, a1.y};
            u64t bb[8] = {dup2(b0.x), dup2(b0.y), dup2(b0.z), dup2(b0.w),
                          dup2(b1.x), dup2(b1.y), dup2(b1.z), dup2(b1.w)};
#pragma unroll
            for (int rp = 0; rp < 4; ++rp)
#pragma unroll
                for (int c = 0; c < 8; ++c) ffma2(acc[rp][c], ap[rp], bb[c]);
        }
        __syncthreads();
    }

#pragma unroll
    for (int rp = 0; rp < 4; ++rp)
#pragma unroll
        for (int par = 0; par < 2; ++par) {
            int m = m0 + ty * 8 + rp * 2 + par;
#pragma unroll
            for (int cg = 0; cg < 2; ++cg) {
                float4 o;
                float2 v0 = *(float2*)&acc[rp][cg * 4 + 0];
                float2 v1 = *(float2*)&acc[rp][cg * 4 + 1];
                float2 v2 = *(float2*)&acc[rp][cg * 4 + 2];
                float2 v3 = *(float2*)&acc[rp][cg * 4 + 3];
                o.x = par ? v0.y : v0.x; o.y = par ? v1.y : v1.x;
                o.z = par ? v2.y : v2.x; o.w = par ? v3.y : v3.x;
                if (IS_QKV) {
                    int which = n0 / D_;
                    int hb = ((n0 % D_) >> 6) + cg;
                    int b = m >> 10, r = m & 1023;
                    float* dst = (which == 0) ? g_q : (which == 1) ? g_k : g_v;
                    *(float4*)&dst[(((size_t)(b * H_ + hb) * N_ + r) << 6) + tx * 4] = o;
                } else {
                    float4 bf = *(const float4*)&bias[n0 + cg * 64 + tx * 4];
                    o.x += bf.x; o.y += bf.y; o.z += bf.z; o.w += bf.w;
                    *(float4*)&out[(size_t)m * D_ + n0 + cg * 64 + tx * 4] = o;
                }
            }
        }
}

// ---------------- bucket-index precompute ----------------
__device__ __forceinline__ int bucket_fn(int d) {
    int ret = (d > 0) ? 16 : 0;
    int n = (d < 0) ? -d : d;
    int v;
    if (n < 8) v = n;
    else { v = 33 - __clz(n * n); v = (v > 15) ? 15 : v; }
    return ret + v;
}

__global__ __launch_bounds__(256) void bidx_kernel(const float* __restrict__ coords) {
    __shared__ short cjx[1024], cjy[1024];
    const int b = blockIdx.y, i0 = blockIdx.x * 64, tid = threadIdx.x;
    for (int t = tid; t < 1024; t += 256) {
        float2 c = *(const float2*)(coords + ((size_t)b * 1024 + t) * 2);
        cjx[t] = (short)(int)(c.x * 128.0f);
        cjy[t] = (short)(int)(c.y * 128.0f);
    }
    __syncthreads();
    unsigned short* outb = g_bidx + (size_t)b * N_ * N_ + (size_t)i0 * N_;
    for (int q = 0; q < 64; ++q) {
        int item = tid + q * 256;
        int i = item >> 8, j = (item & 255) * 4;
        int cx = cjx[i0 + i], cy = cjy[i0 + i];
        ushort4 r;
        r.x = (unsigned short)((bucket_fn(cx - cjx[j]) << 5) | bucket_fn(cy - cjy[j]));
        r.y = (unsigned short)((bucket_fn(cx - cjx[j + 1]) << 5) | bucket_fn(cy - cjy[j + 1]));
        r.z = (unsigned short)((bucket_fn(cx - cjx[j + 2]) << 5) | bucket_fn(cy - cjy[j + 2]));
        r.w = (unsigned short)((bucket_fn(cx - cjx[j + 3]) << 5) | bucket_fn(cy - cjy[j + 3]));
        *(ushort4*)(outb + (size_t)i * N_ + j) = r;
    }
}

// ---------------- attention: i-tile 128, j-tile 64, f32x2 ----------------
#define AT_QT 0
#define AT_KT 8192
#define AT_VS 12544
#define AT_PS 16896
#define AT_TBL 25600
#define AT_EJS 26624
#define ATTN_SMEM_BYTES (26688 * 4)

__global__ __launch_bounds__(256, 2) void attn2_kernel(
    const float* __restrict__ elev, const float* __restrict__ bias_table,
    const float* __restrict__ alphap) {
    extern __shared__ float sm[];
    float(*qt)[128] = (float(*)[128])(sm + AT_QT);
    float(*kt)[68] = (float(*)[68])(sm + AT_KT);
    float(*vs)[68] = (float(*)[68])(sm + AT_VS);
    float(*ps)[68] = (float(*)[68])(sm + AT_PS);
    float* tbl = sm + AT_TBL;
    float* ejs = sm + AT_EJS;

    const int i0 = blockIdx.x * 128, h = blockIdx.y, b = blockIdx.z;
    const int tid = threadIdx.x;
    const int tx = tid & 15, ty = tid >> 4;

    for (int t = tid; t < 1024; t += 256) tbl[t] = bias_table[t * H_ + h];

    const float* qb = g_q + (((size_t)(b * H_ + h) * N_ + i0) << 6);
#pragma unroll
    for (int p = 0; p < 8; ++p) {
        int idx = tid + p * 256;
        int i = idx & 127, dq = idx >> 7;
        float4 f = *(const float4*)(qb + i * 64 + dq * 4);
        qt[dq * 4 + 0][i] = f.x; qt[dq * 4 + 1][i] = f.y;
        qt[dq * 4 + 2][i] = f.z; qt[dq * 4 + 3][i] = f.w;
    }

    float eir[8];
#pragma unroll
    for (int i = 0; i < 8; ++i)
        eir[i] = elev[b * N_ + i0 + ty * 8 + i] * (1.0f / 1000.0f);
    const float alpha = *alphap;

    u64t oacc[8][2];
    float mrow[8], lrow[8];
#pragma unroll
    for (int i = 0; i < 8; ++i) {
        oacc[i][0] = 0ULL; oacc[i][1] = 0ULL;
        mrow[i] = -1e30f; lrow[i] = 0.0f;
    }

    const float* kb0 = g_k + (((size_t)(b * H_ + h) * N_) << 6);
    const float* vb0 = g_v + (((size_t)(b * H_ + h) * N_) << 6);
    const unsigned short* bidxb = g_bidx + (size_t)b * N_ * N_ + (size_t)i0 * N_;

    for (int jt = 0; jt < 16; ++jt) {
        const int j0 = jt * 64;
        __syncthreads();
        const float* kb = kb0 + ((size_t)j0 << 6);
        const float* vb = vb0 + ((size_t)j0 << 6);
#pragma unroll
        for (int p = 0; p < 4; ++p) {
            int idx = tid + p * 256;
            int j = idx & 63, dq = idx >> 6;
            float4 f = *(const float4*)(kb + j * 64 + dq * 4);
            kt[dq * 4 + 0][j] = f.x; kt[dq * 4 + 1][j] = f.y;
            kt[dq * 4 + 2][j] = f.z; kt[dq * 4 + 3][j] = f.w;
            int dv = idx & 15, jv = idx >> 4;
            *(float4*)&vs[jv][dv * 4] = *(const float4*)(vb + jv * 64 + dv * 4);
        }
        if (tid < 64) ejs[tid] = elev[b * N_ + j0 + tid] * (1.0f / 1000.0f);
        __syncthreads();

        u64t s2[4][4];
#pragma unroll
        for (int i = 0; i < 4; i++)
#pragma unroll
            for (int j = 0; j < 4; j++) s2[i][j] = 0ULL;
#pragma unroll 8
        for (int d = 0; d < 64; ++d) {
            ulonglong2 qa0 = *(const ulonglong2*)&qt[d][ty * 8];
            ulonglong2 qa1 = *(const ulonglong2*)&qt[d][ty * 8 + 4];
            float4 kf = *(const float4*)&kt[d][tx * 4];
            u64t ap[4] = {qa0.x, qa0.y, qa1.x, qa1.y};
            u64t bbv[4] = {dup2(kf.x), dup2(kf.y), dup2(kf.z), dup2(kf.w)};
#pragma unroll
            for (int rp = 0; rp < 4; ++rp)
#pragma unroll
                for (int c = 0; c < 4; ++c) ffma2(s2[rp][c], ap[rp], bbv[c]);
        }

#pragma unroll
        for (int i = 0; i < 8; ++i) {
            int rp = i >> 1, hi = i & 1;
            float sv[4];
#pragma unroll
            for (int c = 0; c < 4; ++c) {
                float2 v = *(float2*)&s2[rp][c];
                sv[c] = hi ? v.y : v.x;
            }
            uint2 bx = *(const uint2*)(bidxb + (size_t)(ty * 8 + i) * N_ + j0 + tx * 4);
            int bi[4] = {(int)(bx.x & 0xffff), (int)(bx.x >> 16),
                         (int)(bx.y & 0xffff), (int)(bx.y >> 16)};
            float e_i = eir[i];
#pragma unroll
            for (int c = 0; c < 4; ++c) {
                float ed = ejs[tx * 4 + c] - e_i;
                float eb = fminf(fmaxf(-alpha * fmaxf(ed, 0.f), -10.f), 0.f);
                sv[c] = sv[c] * 0.125f + tbl[bi[c]] + eb;
            }
            float tm = fmaxf(fmaxf(sv[0], sv[1]), fmaxf(sv[2], sv[3]));
            tm = fmaxf(tm, __shfl_xor_sync(0xffffffff, tm, 1));
            tm = fmaxf(tm, __shfl_xor_sync(0xffffffff, tm, 2));
            tm = fmaxf(tm, __shfl_xor_sync(0xffffffff, tm, 4));
            tm = fmaxf(tm, __shfl_xor_sync(0xffffffff, tm, 8));
            float mnew = fmaxf(mrow[i], tm);
            float corr = __expf(mrow[i] - mnew);
            mrow[i] = mnew;
            float p0 = __expf(sv[0] - mnew), p1 = __expf(sv[1] - mnew);
            float p2 = __expf(sv[2] - mnew), p3 = __expf(sv[3] - mnew);
            lrow[i] = lrow[i] * corr + (p0 + p1 + p2 + p3);
            u64t c2 = dup2(corr);
            asm("mul.rn.f32x2 %0, %0, %1;" : "+l"(oacc[i][0]) : "l"(c2));
            asm("mul.rn.f32x2 %0, %0, %1;" : "+l"(oacc[i][1]) : "l"(c2));
            *(float4*)&ps[ty * 8 + i][tx * 4] = make_float4(p0, p1, p2, p3);
        }
        __syncthreads();

#pragma unroll 8
        for (int jj = 0; jj < 64; ++jj) {
            ulonglong2 v2 = *(const ulonglong2*)&vs[jj][tx * 4];
#pragma unroll
            for (int i = 0; i < 8; ++i) {
                u64t pv = dup2(ps[ty * 8 + i][jj]);
                ffma2(oacc[i][0], pv, v2.x);
                ffma2(oacc[i][1], pv, v2.y);
            }
        }
    }

#pragma unroll
    for (int i = 0; i < 8; ++i) {
        float l = lrow[i];
        l += __shfl_xor_sync(0xffffffff, l, 1);
        l += __shfl_xor_sync(0xffffffff, l, 2);
        l += __shfl_xor_sync(0xffffffff, l, 4);
        l += __shfl_xor_sync(0xffffffff, l, 8);
        float inv = 1.0f / l;
        float2 o0 = *(float2*)&oacc[i][0];
        float2 o1 = *(float2*)&oacc[i][1];
        int row = i0 + ty * 8 + i;
        float4 o = make_float4(o0.x * inv, o0.y * inv, o1.x * inv, o1.y * inv);
        *(float4*)&g_ctx[((size_t)(b * N_ + row)) * D_ + h * 64 + tx * 4] = o;
    }
}

extern "C" void kernel_launch(void* const* d_in, const int* in_sizes, int n_in,
                              void* d_out, int out_size) {
    const float* x = (const float*)d_in[0];
    const float* coords = (const float*)d_in[1];
    const float* elev = (const float*)d_in[2];
    const float* W_qkv = (const float*)d_in[3];
    const float* W_proj = (const float*)d_in[4];
    const float* b_proj = (const float*)d_in[5];
    const float* bias_table = (const float*)d_in[6];
    const float* alpha = (const float*)d_in[7];
    float* out = (float*)d_out;

    cudaFuncSetAttribute(attn2_kernel, cudaFuncAttributeMaxDynamicSharedMemorySize,
                         ATTN_SMEM_BYTES);

    bidx_kernel<<<dim3(16, B_), 256>>>(coords);
    gemm128<true><<<dim3(ND3_ / 128, (B_ * N_) / 128), 256>>>(x, W_qkv, nullptr, nullptr);
    attn2_kernel<<<dim3(N_ / 128, H_, B_), 256, ATTN_SMEM_BYTES>>>(elev, bias_table, alpha);
    gemm128<false><<<dim3(D_ / 128, (B_ * N_) / 128), 256>>>(nullptr, W_proj, b_proj, out);
}

// round 5
// speedup vs baseline: 1.7390x; 1.4179x over previous
#include <cuda_runtime.h>
#include <cuda_bf16.h>
#include <cstdint>

#define B_ 4
#define N_ 1024
#define D_ 768
#define H_ 12
#define ND3_ 2304
typedef unsigned long long u64t;

__device__ float g_q[B_ * H_ * N_ * 64];
__device__ float g_k[B_ * H_ * N_ * 64];
__device__ float g_v[B_ * H_ * N_ * 64];
__device__ float g_ctx[B_ * N_ * D_];
__device__ unsigned short g_bidx[(size_t)B_ * N_ * N_];
__device__ __nv_bfloat16 g_a2[4096 * 1536];  // [m][hi(768)|lo(768)]
__device__ __nv_bfloat16 g_b2[2304 * 1536];  // [n][hi|lo]  (W transposed)

__device__ __forceinline__ void ffma2(u64t& d, u64t a, u64t b) {
    asm("fma.rn.f32x2 %0, %1, %2, %0;" : "+l"(d) : "l"(a), "l"(b));
}
__device__ __forceinline__ u64t dup2(float x) {
    u64t r;
    asm("mov.b64 %0, {%1, %1};" : "=l"(r) : "f"(x));
    return r;
}
__device__ __forceinline__ uint32_t smem_u32(const void* p) {
    uint32_t a;
    asm("{ .reg .u64 t; cvta.to.shared.u64 t, %1; cvt.u32.u64 %0, t; }"
        : "=r"(a) : "l"(p));
    return a;
}
__device__ __forceinline__ void mma16816(float* c, const uint32_t* a,
                                         const uint32_t* b) {
    asm volatile(
        "mma.sync.aligned.m16n8k16.row.col.f32.bf16.bf16.f32 "
        "{%0,%1,%2,%3}, {%4,%5,%6,%7}, {%8,%9}, {%0,%1,%2,%3};"
        : "+f"(c[0]), "+f"(c[1]), "+f"(c[2]), "+f"(c[3])
        : "r"(a[0]), "r"(a[1]), "r"(a[2]), "r"(a[3]), "r"(b[0]), "r"(b[1]));
}
__device__ __forceinline__ void ldsm4(uint32_t* r, uint32_t addr) {
    asm volatile("ldmatrix.sync.aligned.m8n8.x4.shared.b16 {%0,%1,%2,%3}, [%4];"
                 : "=r"(r[0]), "=r"(r[1]), "=r"(r[2]), "=r"(r[3]) : "r"(addr));
}
__device__ __forceinline__ void cp16(uint32_t dst, const void* src) {
    asm volatile("cp.async.ca.shared.global [%0], [%1], 16;" :: "r"(dst), "l"(src));
}

// ---------------- mma.sync bf16-split GEMM: 128x128 tile, KC=32 ------------
// Kext = 3*768: pass0 Ah*Bh, pass1 Ah*Bl, pass2 Al*Bh.
template <bool IS_QKV>
__global__ __launch_bounds__(256) void mma_gemm(const float* __restrict__ bias,
                                                float* __restrict__ out) {
    __shared__ __align__(16) char smA[2][128 * 80];
    __shared__ __align__(16) char smB[2][128 * 80];
    const int tid = threadIdx.x, wid = tid >> 5, lid = tid & 31;
    const int m0 = blockIdx.y * 128, n0 = blockIdx.x * 128;
    const int mw = wid >> 2, nw = wid & 3;

    const __nv_bfloat16* a2 = g_a2 + (size_t)m0 * 1536;
    const __nv_bfloat16* b2 = g_b2 + (size_t)n0 * 1536;

    const int lr0 = (tid) >> 2, ls0 = (tid) & 3;
    const int lr1 = (tid + 256) >> 2, ls1 = (tid + 256) & 3;
    uint32_t dA0[2] = {smem_u32(&smA[0][lr0 * 80 + ls0 * 16]),
                       smem_u32(&smA[0][lr1 * 80 + ls1 * 16])};
    uint32_t dA1[2] = {smem_u32(&smA[1][lr0 * 80 + ls0 * 16]),
                       smem_u32(&smA[1][lr1 * 80 + ls1 * 16])};
    uint32_t dB0[2] = {smem_u32(&smB[0][lr0 * 80 + ls0 * 16]),
                       smem_u32(&smB[0][lr1 * 80 + ls1 * 16])};
    uint32_t dB1[2] = {smem_u32(&smB[1][lr0 * 80 + ls0 * 16]),
                       smem_u32(&smB[1][lr1 * 80 + ls1 * 16])};

    float acc[4][4][4];
#pragma unroll
    for (int i = 0; i < 4; i++)
#pragma unroll
        for (int j = 0; j < 4; j++)
#pragma unroll
            for (int k = 0; k < 4; k++) acc[i][j][k] = 0.0f;

    auto load_chunk = [&](int buf, int aoff, int boff) {
        const uint32_t* dA = buf ? dA1 : dA0;
        const uint32_t* dB = buf ? dB1 : dB0;
        cp16(dA[0], a2 + (size_t)lr0 * 1536 + aoff + ls0 * 8);
        cp16(dA[1], a2 + (size_t)lr1 * 1536 + aoff + ls1 * 8);
        cp16(dB[0], b2 + (size_t)lr0 * 1536 + boff + ls0 * 8);
        cp16(dB[1], b2 + (size_t)lr1 * 1536 + boff + ls1 * 8);
        asm volatile("cp.async.commit_group;" ::: "memory");
    };

    load_chunk(0, 0, 0);
    int buf = 0;

    // ldmatrix address bases (lane-dependent, chunk-invariant)
    const int q = lid >> 3, r = lid & 7;
    const int aRow = mw * 64 + (q & 1) * 8 + r;       // + mt*16
    const int aCol = (q >> 1) * 16;                   // + ks*32
    const int bRowE = nw * 32 + (q >> 1) * 8 + r;     // + p*16
    const int bCol = (q & 1) * 16;                    // + ks*32

    for (int c = 0; c < 72; c++) {
        asm volatile("cp.async.wait_group 0;" ::: "memory");
        __syncthreads();
        if (c < 71) {
            int cn = c + 1, p = cn / 24, cc = cn % 24;
            load_chunk(buf ^ 1, (p == 2 ? 768 : 0) + cc * 32,
                       (p == 1 ? 768 : 0) + cc * 32);
        }
        uint32_t sAb = smem_u32(&smA[buf][0]);
        uint32_t sBb = smem_u32(&smB[buf][0]);
#pragma unroll
        for (int ks = 0; ks < 2; ks++) {
            int koff = ks * 32;
            uint32_t bfr[4][2];
#pragma unroll
            for (int p = 0; p < 2; p++) {
                uint32_t t[4];
                ldsm4(t, sBb + (bRowE + p * 16) * 80 + koff + bCol);
                bfr[p * 2 + 0][0] = t[0];
                bfr[p * 2 + 0][1] = t[1];
                bfr[p * 2 + 1][0] = t[2];
                bfr[p * 2 + 1][1] = t[3];
            }
#pragma unroll
            for (int mt = 0; mt < 4; mt++) {
                uint32_t afr[4];
                ldsm4(afr, sAb + (aRow + mt * 16) * 80 + koff + aCol);
#pragma unroll
                for (int nt = 0; nt < 4; nt++) mma16816(acc[mt][nt], afr, bfr[nt]);
            }
        }
        buf ^= 1;
    }

    // epilogue
#pragma unroll
    for (int mt = 0; mt < 4; mt++) {
#pragma unroll
        for (int half = 0; half < 2; half++) {
            int m = m0 + mw * 64 + mt * 16 + (lid >> 2) + half * 8;
            int mb = m >> 10, mr = m & 1023;
#pragma unroll
            for (int nt = 0; nt < 4; nt++) {
                int ng = n0 + nw * 32 + nt * 8 + 2 * (lid & 3);
                float2 v =
                    make_float2(acc[mt][nt][half * 2], acc[mt][nt][half * 2 + 1]);
                if (IS_QKV) {
                    int which = ng / D_, nm = ng % D_, hh = nm >> 6, c0 = nm & 63;
                    float* dst = (which == 0) ? g_q : (which == 1) ? g_k : g_v;
                    *(float2*)&dst[(((size_t)(mb * H_ + hh) * N_ + mr) << 6) + c0] = v;
                } else {
                    v.x += bias[ng];
                    v.y += bias[ng + 1];
                    *(float2*)&out[(size_t)m * D_ + ng] = v;
                }
            }
        }
    }
}

// ---------------- bf16 hi/lo split preps ----------------
template <bool FROM_CTX>
__global__ __launch_bounds__(256) void split_a(const float* __restrict__ Xp) {
    const float* X = FROM_CTX ? (const float*)g_ctx : Xp;
    int idx = blockIdx.x * 256 + threadIdx.x;
    float4 v = ((const float4*)X)[idx];
    int m = idx / 192, kq = (idx % 192) * 4;
    __nv_bfloat16 h0 = __float2bfloat16(v.x), h1 = __float2bfloat16(v.y);
    __nv_bfloat16 h2 = __float2bfloat16(v.z), h3 = __float2bfloat16(v.w);
    __nv_bfloat16 l0 = __float2bfloat16(v.x - __bfloat162float(h0));
    __nv_bfloat16 l1 = __float2bfloat16(v.y - __bfloat162float(h1));
    __nv_bfloat16 l2 = __float2bfloat16(v.z - __bfloat162float(h2));
    __nv_bfloat16 l3 = __float2bfloat16(v.w - __bfloat162float(h3));
    __nv_bfloat16* rr = g_a2 + (size_t)m * 1536 + kq;
    rr[0] = h0; rr[1] = h1; rr[2] = h2; rr[3] = h3;
    rr[768] = l0; rr[769] = l1; rr[770] = l2; rr[771] = l3;
}

__global__ void split_wt(const float* __restrict__ W, int ncols) {
    __shared__ float t[32][33];
    int k0 = blockIdx.y * 32, n0 = blockIdx.x * 32;
    int tx = threadIdx.x, ty = threadIdx.y;  // (32,8)
#pragma unroll
    for (int i = 0; i < 4; i++)
        t[ty * 4 + i][tx] = W[(size_t)(k0 + ty * 4 + i) * ncols + n0 + tx];
    __syncthreads();
#pragma unroll
    for (int i = 0; i < 4; i++) {
        int n = n0 + ty * 4 + i;
        float x = t[tx][ty * 4 + i];
        __nv_bfloat16 h = __float2bfloat16(x);
        __nv_bfloat16 l = __float2bfloat16(x - __bfloat162float(h));
        g_b2[(size_t)n * 1536 + k0 + tx] = h;
        g_b2[(size_t)n * 1536 + 768 + k0 + tx] = l;
    }
}

// ---------------- bucket-index precompute ----------------
__device__ __forceinline__ int bucket_fn(int d) {
    int ret = (d > 0) ? 16 : 0;
    int n = (d < 0) ? -d : d;
    int v;
    if (n < 8) v = n;
    else { v = 33 - __clz(n * n); v = (v > 15) ? 15 : v; }
    return ret + v;
}

__global__ __launch_bounds__(256) void bidx_kernel(const float* __restrict__ coords) {
    __shared__ short cjx[1024], cjy[1024];
    const int b = blockIdx.y, i0 = blockIdx.x * 64, tid = threadIdx.x;
    for (int t = tid; t < 1024; t += 256) {
        float2 c = *(const float2*)(coords + ((size_t)b * 1024 + t) * 2);
        cjx[t] = (short)(int)(c.x * 128.0f);
        cjy[t] = (short)(int)(c.y * 128.0f);
    }
    __syncthreads();
    unsigned short* outb = g_bidx + (size_t)b * N_ * N_ + (size_t)i0 * N_;
    for (int qq = 0; qq < 64; ++qq) {
        int item = tid + qq * 256;
        int i = item >> 8, j = (item & 255) * 4;
        int cx = cjx[i0 + i], cy = cjy[i0 + i];
        ushort4 r;
        r.x = (unsigned short)((bucket_fn(cx - cjx[j]) << 5) | bucket_fn(cy - cjy[j]));
        r.y = (unsigned short)((bucket_fn(cx - cjx[j + 1]) << 5) | bucket_fn(cy - cjy[j + 1]));
        r.z = (unsigned short)((bucket_fn(cx - cjx[j + 2]) << 5) | bucket_fn(cy - cjy[j + 2]));
        r.w = (unsigned short)((bucket_fn(cx - cjx[j + 3]) << 5) | bucket_fn(cy - cjy[j + 3]));
        *(ushort4*)(outb + (size_t)i * N_ + j) = r;
    }
}

// ---------------- attention (R3, passing) ----------------
#define AT_QT 0
#define AT_KT 8192
#define AT_VS 12544
#define AT_PS 16896
#define AT_TBL 25600
#define AT_EJS 26624
#define ATTN_SMEM_BYTES (26688 * 4)

__global__ __launch_bounds__(256, 2) void attn2_kernel(
    const float* __restrict__ elev, const float* __restrict__ bias_table,
    const float* __restrict__ alphap) {
    extern __shared__ float smf[];
    float(*qt)[128] = (float(*)[128])(smf + AT_QT);
    float(*kt)[68] = (float(*)[68])(smf + AT_KT);
    float(*vs)[68] = (float(*)[68])(smf + AT_VS);
    float(*ps)[68] = (float(*)[68])(smf + AT_PS);
    float* tbl = smf + AT_TBL;
    float* ejs = smf + AT_EJS;

    const int i0 = blockIdx.x * 128, h = blockIdx.y, b = blockIdx.z;
    const int tid = threadIdx.x;
    const int tx = tid & 15, ty = tid >> 4;

    for (int t = tid; t < 1024; t += 256) tbl[t] = bias_table[t * H_ + h];

    const float* qb = g_q + (((size_t)(b * H_ + h) * N_ + i0) << 6);
#pragma unroll
    for (int p = 0; p < 8; ++p) {
        int idx = tid + p * 256;
        int i = idx & 127, dq = idx >> 7;
        float4 f = *(const float4*)(qb + i * 64 + dq * 4);
        qt[dq * 4 + 0][i] = f.x; qt[dq * 4 + 1][i] = f.y;
        qt[dq * 4 + 2][i] = f.z; qt[dq * 4 + 3][i] = f.w;
    }

    float eir[8];
#pragma unroll
    for (int i = 0; i < 8; ++i)
        eir[i] = elev[b * N_ + i0 + ty * 8 + i] * (1.0f / 1000.0f);
    const float alpha = *alphap;

    u64t oacc[8][2];
    float mrow[8], lrow[8];
#pragma unroll
    for (int i = 0; i < 8; ++i) {
        oacc[i][0] = 0ULL; oacc[i][1] = 0ULL;
        mrow[i] = -1e30f; lrow[i] = 0.0f;
    }

    const float* kb0 = g_k + (((size_t)(b * H_ + h) * N_) << 6);
    const float* vb0 = g_v + (((size_t)(b * H_ + h) * N_) << 6);
    const unsigned short* bidxb = g_bidx + (size_t)b * N_ * N_ + (size_t)i0 * N_;

    for (int jt = 0; jt < 16; ++jt) {
        const int j0 = jt * 64;
        __syncthreads();
        const float* kb = kb0 + ((size_t)j0 << 6);
        const float* vb = vb0 + ((size_t)j0 << 6);
#pragma unroll
        for (int p = 0; p < 4; ++p) {
            int idx = tid + p * 256;
            int j = idx & 63, dq = idx >> 6;
            float4 f = *(const float4*)(kb + j * 64 + dq * 4);
            kt[dq * 4 + 0][j] = f.x; kt[dq * 4 + 1][j] = f.y;
            kt[dq * 4 + 2][j] = f.z; kt[dq * 4 + 3][j] = f.w;
            int dv = idx & 15, jv = idx >> 4;
            *(float4*)&vs[jv][dv * 4] = *(const float4*)(vb + jv * 64 + dv * 4);
        }
        if (tid < 64) ejs[tid] = elev[b * N_ + j0 + tid] * (1.0f / 1000.0f);
        __syncthreads();

        u64t s2[4][4];
#pragma unroll
        for (int i = 0; i < 4; i++)
#pragma unroll
            for (int j = 0; j < 4; j++) s2[i][j] = 0ULL;
#pragma unroll 8
        for (int d = 0; d < 64; ++d) {
            ulonglong2 qa0 = *(const ulonglong2*)&qt[d][ty * 8];
            ulonglong2 qa1 = *(const ulonglong2*)&qt[d][ty * 8 + 4];
            float4 kf = *(const float4*)&kt[d][tx * 4];
            u64t ap[4] = {qa0.x, qa0.y, qa1.x, qa1.y};
            u64t bbv[4] = {dup2(kf.x), dup2(kf.y), dup2(kf.z), dup2(kf.w)};
#pragma unroll
            for (int rp = 0; rp < 4; ++rp)
#pragma unroll
                for (int c = 0; c < 4; ++c) ffma2(s2[rp][c], ap[rp], bbv[c]);
        }

#pragma unroll
        for (int i = 0; i < 8; ++i) {
            int rp = i >> 1, hi = i & 1;
            float sv[4];
#pragma unroll
            for (int c = 0; c < 4; ++c) {
                float2 v = *(float2*)&s2[rp][c];
                sv[c] = hi ? v.y : v.x;
            }
            uint2 bx = *(const uint2*)(bidxb + (size_t)(ty * 8 + i) * N_ + j0 + tx * 4);
            int bi[4] = {(int)(bx.x & 0xffff), (int)(bx.x >> 16),
                         (int)(bx.y & 0xffff), (int)(bx.y >> 16)};
            float e_i = eir[i];
#pragma unroll
            for (int c = 0; c < 4; ++c) {
                float ed = ejs[tx * 4 + c] - e_i;
                float eb = fminf(fmaxf(-alpha * fmaxf(ed, 0.f), -10.f), 0.f);
                sv[c] = sv[c] * 0.125f + tbl[bi[c]] + eb;
            }
            float tm = fmaxf(fmaxf(sv[0], sv[1]), fmaxf(sv[2], sv[3]));
            tm = fmaxf(tm, __shfl_xor_sync(0xffffffff, tm, 1));
            tm = fmaxf(tm, __shfl_xor_sync(0xffffffff, tm, 2));
            tm = fmaxf(tm, __shfl_xor_sync(0xffffffff, tm, 4));
            tm = fmaxf(tm, __shfl_xor_sync(0xffffffff, tm, 8));
            float mnew = fmaxf(mrow[i], tm);
            float corr = __expf(mrow[i] - mnew);
            mrow[i] = mnew;
            float p0 = __expf(sv[0] - mnew), p1 = __expf(sv[1] - mnew);
            float p2 = __expf(sv[2] - mnew), p3 = __expf(sv[3] - mnew);
            lrow[i] = lrow[i] * corr + (p0 + p1 + p2 + p3);
            u64t c2 = dup2(corr);
            asm("mul.rn.f32x2 %0, %0, %1;" : "+l"(oacc[i][0]) : "l"(c2));
            asm("mul.rn.f32x2 %0, %0, %1;" : "+l"(oacc[i][1]) : "l"(c2));
            *(float4*)&ps[ty * 8 + i][tx * 4] = make_float4(p0, p1, p2, p3);
        }
        __syncthreads();

#pragma unroll 8
        for (int jj = 0; jj < 64; ++jj) {
            ulonglong2 v2 = *(const ulonglong2*)&vs[jj][tx * 4];
#pragma unroll
            for (int i = 0; i < 8; ++i) {
                u64t pv = dup2(ps[ty * 8 + i][jj]);
                ffma2(oacc[i][0], pv, v2.x);
                ffma2(oacc[i][1], pv, v2.y);
            }
        }
    }

#pragma unroll
    for (int i = 0; i < 8; ++i) {
        float l = lrow[i];
        l += __shfl_xor_sync(0xffffffff, l, 1);
        l += __shfl_xor_sync(0xffffffff, l, 2);
        l += __shfl_xor_sync(0xffffffff, l, 4);
        l += __shfl_xor_sync(0xffffffff, l, 8);
        float inv = 1.0f / l;
        float2 o0 = *(float2*)&oacc[i][0];
        float2 o1 = *(float2*)&oacc[i][1];
        int row = i0 + ty * 8 + i;
        float4 o = make_float4(o0.x * inv, o0.y * inv, o1.x * inv, o1.y * inv);
        *(float4*)&g_ctx[((size_t)(b * N_ + row)) * D_ + h * 64 + tx * 4] = o;
    }
}

extern "C" void kernel_launch(void* const* d_in, const int* in_sizes, int n_in,
                              void* d_out, int out_size) {
    const float* x = (const float*)d_in[0];
    const float* coords = (const float*)d_in[1];
    const float* elev = (const float*)d_in[2];
    const float* W_qkv = (const float*)d_in[3];
    const float* W_proj = (const float*)d_in[4];
    const float* b_proj = (const float*)d_in[5];
    const float* bias_table = (const float*)d_in[6];
    const float* alpha = (const float*)d_in[7];
    float* out = (float*)d_out;

    cudaFuncSetAttribute(attn2_kernel, cudaFuncAttributeMaxDynamicSharedMemorySize,
                         ATTN_SMEM_BYTES);

    split_a<false><<<3072, 256>>>(x);
    split_wt<<<dim3(ND3_ / 32, 24), dim3(32, 8)>>>(W_qkv, ND3_);
    mma_gemm<true><<<dim3(ND3_ / 128, 32), 256>>>(nullptr, nullptr);
    bidx_kernel<<<dim3(16, B_), 256>>>(coords);
    attn2_kernel<<<dim3(N_ / 128, H_, B_), 256, ATTN_SMEM_BYTES>>>(elev, bias_table, alpha);
    split_a<true><<<3072, 256>>>(nullptr);
    split_wt<<<dim3(D_ / 32, 24), dim3(32, 8)>>>(W_proj, D_);
    mma_gemm<false><<<dim3(D_ / 128, 32), 256>>>(b_proj, out);
}

// round 6
// speedup vs baseline: 1.7557x; 1.0096x over previous
#include <cuda_runtime.h>
#include <cuda_bf16.h>
#include <cstdint>

#define B_ 4
#define N_ 1024
#define D_ 768
#define H_ 12
#define ND3_ 2304
typedef unsigned long long u64t;

__device__ float g_q[B_ * H_ * N_ * 64];
__device__ float g_k[B_ * H_ * N_ * 64];
__device__ float g_v[B_ * H_ * N_ * 64];
__device__ unsigned short g_bidx[(size_t)B_ * N_ * N_];
__device__ __nv_bfloat16 g_a2[4096 * 1536];  // [m][hi(768)|lo(768)]
__device__ __nv_bfloat16 g_b2[2304 * 1536];  // [n][hi|lo]  (W transposed)

__device__ __forceinline__ void ffma2(u64t& d, u64t a, u64t b) {
    asm("fma.rn.f32x2 %0, %1, %2, %0;" : "+l"(d) : "l"(a), "l"(b));
}
__device__ __forceinline__ u64t dup2(float x) {
    u64t r;
    asm("mov.b64 %0, {%1, %1};" : "=l"(r) : "f"(x));
    return r;
}
__device__ __forceinline__ uint32_t smem_u32(const void* p) {
    uint32_t a;
    asm("{ .reg .u64 t; cvta.to.shared.u64 t, %1; cvt.u32.u64 %0, t; }"
        : "=r"(a) : "l"(p));
    return a;
}
__device__ __forceinline__ void mma16816(float* c, const uint32_t* a,
                                         const uint32_t* b) {
    asm volatile(
        "mma.sync.aligned.m16n8k16.row.col.f32.bf16.bf16.f32 "
        "{%0,%1,%2,%3}, {%4,%5,%6,%7}, {%8,%9}, {%0,%1,%2,%3};"
        : "+f"(c[0]), "+f"(c[1]), "+f"(c[2]), "+f"(c[3])
        : "r"(a[0]), "r"(a[1]), "r"(a[2]), "r"(a[3]), "r"(b[0]), "r"(b[1]));
}
__device__ __forceinline__ void ldsm4(uint32_t* r, uint32_t addr) {
    asm volatile("ldmatrix.sync.aligned.m8n8.x4.shared.b16 {%0,%1,%2,%3}, [%4];"
                 : "=r"(r[0]), "=r"(r[1]), "=r"(r[2]), "=r"(r[3]) : "r"(addr));
}
__device__ __forceinline__ void cp16(uint32_t dst, const void* src) {
    asm volatile("cp.async.ca.shared.global [%0], [%1], 16;" :: "r"(dst), "l"(src));
}

// ------------- mma.sync bf16-split GEMM: 128x128 tile, KC=32, 3-stage -------
// Kext = 3*768: pass0 Ah*Bh, pass1 Ah*Bl, pass2 Al*Bh.
#define GSTAGE_BYTES 20480  // A 128*80 + B 128*80
#define GEMM_SMEM (3 * GSTAGE_BYTES)

template <bool IS_QKV>
__global__ __launch_bounds__(256) void mma_gemm(const float* __restrict__ bias,
                                                float* __restrict__ out) {
    extern __shared__ char smem[];
    const int tid = threadIdx.x, wid = tid >> 5, lid = tid & 31;
    const int m0 = blockIdx.y * 128, n0 = blockIdx.x * 128;
    const int mw = wid >> 2, nw = wid & 3;
    const uint32_t sbase = smem_u32(smem);

    const __nv_bfloat16* a2 = g_a2 + (size_t)m0 * 1536;
    const __nv_bfloat16* b2 = g_b2 + (size_t)n0 * 1536;

    const int lr0 = tid >> 2, ls0 = tid & 3;
    const int lr1 = (tid + 256) >> 2, ls1 = (tid + 256) & 3;

    float acc[4][4][4];
#pragma unroll
    for (int i = 0; i < 4; i++)
#pragma unroll
        for (int j = 0; j < 4; j++)
#pragma unroll
            for (int k = 0; k < 4; k++) acc[i][j][k] = 0.0f;

    auto load_chunk = [&](int c, int s) {
        int p = c / 24, cc = c % 24;
        int aoff = (p == 2 ? 768 : 0) + cc * 32;
        int boff = (p == 1 ? 768 : 0) + cc * 32;
        uint32_t da = sbase + s * GSTAGE_BYTES;
        uint32_t db = da + 10240;
        cp16(da + lr0 * 80 + ls0 * 16, a2 + (size_t)lr0 * 1536 + aoff + ls0 * 8);
        cp16(da + lr1 * 80 + ls1 * 16, a2 + (size_t)lr1 * 1536 + aoff + ls1 * 8);
        cp16(db + lr0 * 80 + ls0 * 16, b2 + (size_t)lr0 * 1536 + boff + ls0 * 8);
        cp16(db + lr1 * 80 + ls1 * 16, b2 + (size_t)lr1 * 1536 + boff + ls1 * 8);
        asm volatile("cp.async.commit_group;" ::: "memory");
    };

    load_chunk(0, 0);
    load_chunk(1, 1);

    // ldmatrix lane bases (chunk-invariant)
    const int q = lid >> 3, r = lid & 7;
    const int aRow = mw * 64 + (q & 1) * 8 + r;    // + mt*16
    const int aCol = (q >> 1) * 16;                // + ks*32
    const int bRowE = nw * 32 + (q >> 1) * 8 + r;  // + p*16
    const int bCol = (q & 1) * 16;                 // + ks*32

    int s = 0, sn = 2;
    for (int c = 0; c < 72; c++) {
        asm volatile("cp.async.wait_group 1;" ::: "memory");
        __syncthreads();
        if (c + 2 < 72) {
            load_chunk(c + 2, sn);
            if (++sn == 3) sn = 0;
        }
        uint32_t sAb = sbase + s * GSTAGE_BYTES;
        uint32_t sBb = sAb + 10240;
#pragma unroll
        for (int ks = 0; ks < 2; ks++) {
            int koff = ks * 32;
            uint32_t bfr[4][2];
#pragma unroll
            for (int p = 0; p < 2; p++) {
                uint32_t t[4];
                ldsm4(t, sBb + (bRowE + p * 16) * 80 + koff + bCol);
                bfr[p * 2 + 0][0] = t[0];
                bfr[p * 2 + 0][1] = t[1];
                bfr[p * 2 + 1][0] = t[2];
                bfr[p * 2 + 1][1] = t[3];
            }
#pragma unroll
            for (int mt = 0; mt < 4; mt++) {
                uint32_t afr[4];
                ldsm4(afr, sAb + (aRow + mt * 16) * 80 + koff + aCol);
#pragma unroll
                for (int nt = 0; nt < 4; nt++) mma16816(acc[mt][nt], afr, bfr[nt]);
            }
        }
        if (++s == 3) s = 0;
    }

    // epilogue
#pragma unroll
    for (int mt = 0; mt < 4; mt++) {
#pragma unroll
        for (int half = 0; half < 2; half++) {
            int m = m0 + mw * 64 + mt * 16 + (lid >> 2) + half * 8;
            int mb = m >> 10, mr = m & 1023;
#pragma unroll
            for (int nt = 0; nt < 4; nt++) {
                int ng = n0 + nw * 32 + nt * 8 + 2 * (lid & 3);
                float2 v =
                    make_float2(acc[mt][nt][half * 2], acc[mt][nt][half * 2 + 1]);
                if (IS_QKV) {
                    int which = ng / D_, nm = ng % D_, hh = nm >> 6, c0 = nm & 63;
                    float* dst = (which == 0) ? g_q : (which == 1) ? g_k : g_v;
                    *(float2*)&dst[(((size_t)(mb * H_ + hh) * N_ + mr) << 6) + c0] = v;
                } else {
                    v.x += bias[ng];
                    v.y += bias[ng + 1];
                    *(float2*)&out[(size_t)m * D_ + ng] = v;
                }
            }
        }
    }
}

// ---------------- bf16 hi/lo split preps ----------------
__global__ __launch_bounds__(256) void split_a(const float* __restrict__ X) {
    int idx = blockIdx.x * 256 + threadIdx.x;
    float4 v = ((const float4*)X)[idx];
    int m = idx / 192, kq = (idx % 192) * 4;
    __nv_bfloat16 h0 = __float2bfloat16(v.x), h1 = __float2bfloat16(v.y);
    __nv_bfloat16 h2 = __float2bfloat16(v.z), h3 = __float2bfloat16(v.w);
    __nv_bfloat16 l0 = __float2bfloat16(v.x - __bfloat162float(h0));
    __nv_bfloat16 l1 = __float2bfloat16(v.y - __bfloat162float(h1));
    __nv_bfloat16 l2 = __float2bfloat16(v.z - __bfloat162float(h2));
    __nv_bfloat16 l3 = __float2bfloat16(v.w - __bfloat162float(h3));
    __nv_bfloat16* rr = g_a2 + (size_t)m * 1536 + kq;
    rr[0] = h0; rr[1] = h1; rr[2] = h2; rr[3] = h3;
    rr[768] = l0; rr[769] = l1; rr[770] = l2; rr[771] = l3;
}

__global__ void split_wt(const float* __restrict__ W, int ncols) {
    __shared__ float t[32][33];
    int k0 = blockIdx.y * 32, n0 = blockIdx.x * 32;
    int tx = threadIdx.x, ty = threadIdx.y;  // (32,8)
#pragma unroll
    for (int i = 0; i < 4; i++)
        t[ty * 4 + i][tx] = W[(size_t)(k0 + ty * 4 + i) * ncols + n0 + tx];
    __syncthreads();
#pragma unroll
    for (int i = 0; i < 4; i++) {
        int n = n0 + ty * 4 + i;
        float x = t[tx][ty * 4 + i];
        __nv_bfloat16 h = __float2bfloat16(x);
        __nv_bfloat16 l = __float2bfloat16(x - __bfloat162float(h));
        g_b2[(size_t)n * 1536 + k0 + tx] = h;
        g_b2[(size_t)n * 1536 + 768 + k0 + tx] = l;
    }
}

// ---------------- bucket-index precompute (256 CTAs) ----------------
__device__ __forceinline__ int bucket_fn(int d) {
    int ret = (d > 0) ? 16 : 0;
    int n = (d < 0) ? -d : d;
    int v;
    if (n < 8) v = n;
    else { v = 33 - __clz(n * n); v = (v > 15) ? 15 : v; }
    return ret + v;
}

__global__ __launch_bounds__(256) void bidx_kernel(const float* __restrict__ coords) {
    __shared__ short cjx[1024], cjy[1024];
    const int b = blockIdx.y, i0 = blockIdx.x * 16, tid = threadIdx.x;
    for (int t = tid; t < 1024; t += 256) {
        float2 c = *(const float2*)(coords + ((size_t)b * 1024 + t) * 2);
        cjx[t] = (short)(int)(c.x * 128.0f);
        cjy[t] = (short)(int)(c.y * 128.0f);
    }
    __syncthreads();
    unsigned short* outb = g_bidx + (size_t)b * N_ * N_ + (size_t)i0 * N_;
#pragma unroll
    for (int qq = 0; qq < 16; ++qq) {
        int item = tid + qq * 256;
        int i = item >> 8, j = (item & 255) * 4;
        int cx = cjx[i0 + i], cy = cjy[i0 + i];
        ushort4 r;
        r.x = (unsigned short)((bucket_fn(cx - cjx[j]) << 5) | bucket_fn(cy - cjy[j]));
        r.y = (unsigned short)((bucket_fn(cx - cjx[j + 1]) << 5) | bucket_fn(cy - cjy[j + 1]));
        r.z = (unsigned short)((bucket_fn(cx - cjx[j + 2]) << 5) | bucket_fn(cy - cjy[j + 2]));
        r.w = (unsigned short)((bucket_fn(cx - cjx[j + 3]) << 5) | bucket_fn(cy - cjy[j + 3]));
        *(ushort4*)(outb + (size_t)i * N_ + j) = r;
    }
}

// ---------------- attention (epilogue writes bf16 split to g_a2) -----------
#define AT_QT 0
#define AT_KT 8192
#define AT_VS 12544
#define AT_PS 16896
#define AT_TBL 25600
#define AT_EJS 26624
#define ATTN_SMEM_BYTES (26688 * 4)

__global__ __launch_bounds__(256, 2) void attn2_kernel(
    const float* __restrict__ elev, const float* __restrict__ bias_table,
    const float* __restrict__ alphap) {
    extern __shared__ float smf[];
    float(*qt)[128] = (float(*)[128])(smf + AT_QT);
    float(*kt)[68] = (float(*)[68])(smf + AT_KT);
    float(*vs)[68] = (float(*)[68])(smf + AT_VS);
    float(*ps)[68] = (float(*)[68])(smf + AT_PS);
    float* tbl = smf + AT_TBL;
    float* ejs = smf + AT_EJS;

    const int i0 = blockIdx.x * 128, h = blockIdx.y, b = blockIdx.z;
    const int tid = threadIdx.x;
    const int tx = tid & 15, ty = tid >> 4;

    for (int t = tid; t < 1024; t += 256) tbl[t] = bias_table[t * H_ + h];

    const float* qb = g_q + (((size_t)(b * H_ + h) * N_ + i0) << 6);
#pragma unroll
    for (int p = 0; p < 8; ++p) {
        int idx = tid + p * 256;
        int i = idx & 127, dq = idx >> 7;
        float4 f = *(const float4*)(qb + i * 64 + dq * 4);
        qt[dq * 4 + 0][i] = f.x; qt[dq * 4 + 1][i] = f.y;
        qt[dq * 4 + 2][i] = f.z; qt[dq * 4 + 3][i] = f.w;
    }

    float eir[8];
#pragma unroll
    for (int i = 0; i < 8; ++i)
        eir[i] = elev[b * N_ + i0 + ty * 8 + i] * (1.0f / 1000.0f);
    const float alpha = *alphap;

    u64t oacc[8][2];
    float mrow[8], lrow[8];
#pragma unroll
    for (int i = 0; i < 8; ++i) {
        oacc[i][0] = 0ULL; oacc[i][1] = 0ULL;
        mrow[i] = -1e30f; lrow[i] = 0.0f;
    }

    const float* kb0 = g_k + (((size_t)(b * H_ + h) * N_) << 6);
    const float* vb0 = g_v + (((size_t)(b * H_ + h) * N_) << 6);
    const unsigned short* bidxb = g_bidx + (size_t)b * N_ * N_ + (size_t)i0 * N_;

    for (int jt = 0; jt < 16; ++jt) {
        const int j0 = jt * 64;
        __syncthreads();
        const float* kb = kb0 + ((size_t)j0 << 6);
        const float* vb = vb0 + ((size_t)j0 << 6);
#pragma unroll
        for (int p = 0; p < 4; ++p) {
            int idx = tid + p * 256;
            int j = idx & 63, dq = idx >> 6;
            float4 f = *(const float4*)(kb + j * 64 + dq * 4);
            kt[dq * 4 + 0][j] = f.x; kt[dq * 4 + 1][j] = f.y;
            kt[dq * 4 + 2][j] = f.z; kt[dq * 4 + 3][j] = f.w;
            int dv = idx & 15, jv = idx >> 4;
            *(float4*)&vs[jv][dv * 4] = *(const float4*)(vb + jv * 64 + dv * 4);
        }
        if (tid < 64) ejs[tid] = elev[b * N_ + j0 + tid] * (1.0f / 1000.0f);
        __syncthreads();

        u64t s2[4][4];
#pragma unroll
        for (int i = 0; i < 4; i++)
#pragma unroll
            for (int j = 0; j < 4; j++) s2[i][j] = 0ULL;
#pragma unroll 8
        for (int d = 0; d < 64; ++d) {
            ulonglong2 qa0 = *(const ulonglong2*)&qt[d][ty * 8];
            ulonglong2 qa1 = *(const ulonglong2*)&qt[d][ty * 8 + 4];
            float4 kf = *(const float4*)&kt[d][tx * 4];
            u64t ap[4] = {qa0.x, qa0.y, qa1.x, qa1.y};
            u64t bbv[4] = {dup2(kf.x), dup2(kf.y), dup2(kf.z), dup2(kf.w)};
#pragma unroll
            for (int rp = 0; rp < 4; ++rp)
#pragma unroll
                for (int c = 0; c < 4; ++c) ffma2(s2[rp][c], ap[rp], bbv[c]);
        }

#pragma unroll
        for (int i = 0; i < 8; ++i) {
            int rp = i >> 1, hi = i & 1;
            float sv[4];
#pragma unroll
            for (int c = 0; c < 4; ++c) {
                float2 v = *(float2*)&s2[rp][c];
                sv[c] = hi ? v.y : v.x;
            }
            uint2 bx = *(const uint2*)(bidxb + (size_t)(ty * 8 + i) * N_ + j0 + tx * 4);
            int bi[4] = {(int)(bx.x & 0xffff), (int)(bx.x >> 16),
                         (int)(bx.y & 0xffff), (int)(bx.y >> 16)};
            float e_i = eir[i];
#pragma unroll
            for (int c = 0; c < 4; ++c) {
                float ed = ejs[tx * 4 + c] - e_i;
                float eb = fminf(fmaxf(-alpha * fmaxf(ed, 0.f), -10.f), 0.f);
                sv[c] = sv[c] * 0.125f + tbl[bi[c]] + eb;
            }
            float tm = fmaxf(fmaxf(sv[0], sv[1]), fmaxf(sv[2], sv[3]));
            tm = fmaxf(tm, __shfl_xor_sync(0xffffffff, tm, 1));
            tm = fmaxf(tm, __shfl_xor_sync(0xffffffff, tm, 2));
            tm = fmaxf(tm, __shfl_xor_sync(0xffffffff, tm, 4));
            tm = fmaxf(tm, __shfl_xor_sync(0xffffffff, tm, 8));
            float mnew = fmaxf(mrow[i], tm);
            float corr = __expf(mrow[i] - mnew);
            mrow[i] = mnew;
            float p0 = __expf(sv[0] - mnew), p1 = __expf(sv[1] - mnew);
            float p2 = __expf(sv[2] - mnew), p3 = __expf(sv[3] - mnew);
            lrow[i] = lrow[i] * corr + (p0 + p1 + p2 + p3);
            u64t c2 = dup2(corr);
            asm("mul.rn.f32x2 %0, %0, %1;" : "+l"(oacc[i][0]) : "l"(c2));
            asm("mul.rn.f32x2 %0, %0, %1;" : "+l"(oacc[i][1]) : "l"(c2));
            *(float4*)&ps[ty * 8 + i][tx * 4] = make_float4(p0, p1, p2, p3);
        }
        __syncthreads();

#pragma unroll 8
        for (int jj = 0; jj < 64; ++jj) {
            ulonglong2 v2 = *(const ulonglong2*)&vs[jj][tx * 4];
#pragma unroll
            for (int i = 0; i < 8; ++i) {
                u64t pv = dup2(ps[ty * 8 + i][jj]);
                ffma2(oacc[i][0], pv, v2.x);
                ffma2(oacc[i][1], pv, v2.y);
            }
        }
    }

#pragma unroll
    for (int i = 0; i < 8; ++i) {
        float l = lrow[i];
        l += __shfl_xor_sync(0xffffffff, l, 1);
        l += __shfl_xor_sync(0xffffffff, l, 2);
        l += __shfl_xor_sync(0xffffffff, l, 4);
        l += __shfl_xor_sync(0xffffffff, l, 8);
        float inv = 1.0f / l;
        float2 o0 = *(float2*)&oacc[i][0];
        float2 o1 = *(float2*)&oacc[i][1];
        int row = i0 + ty * 8 + i;
        float ov[4] = {o0.x * inv, o0.y * inv, o1.x * inv, o1.y * inv};
        // write bf16 hi/lo split directly (feeds proj GEMM)
        __nv_bfloat16* rr = g_a2 + (size_t)(b * N_ + row) * 1536 + h * 64 + tx * 4;
        __nv_bfloat16 hbuf[4], lbuf[4];
#pragma unroll
        for (int c = 0; c < 4; ++c) {
            hbuf[c] = __float2bfloat16(ov[c]);
            lbuf[c] = __float2bfloat16(ov[c] - __bfloat162float(hbuf[c]));
        }
        *(uint2*)rr = *(uint2*)hbuf;
        *(uint2*)(rr + 768) = *(uint2*)lbuf;
    }
}

extern "C" void kernel_launch(void* const* d_in, const int* in_sizes, int n_in,
                              void* d_out, int out_size) {
    const float* x = (const float*)d_in[0];
    const float* coords = (const float*)d_in[1];
    const float* elev = (const float*)d_in[2];
    const float* W_qkv = (const float*)d_in[3];
    const float* W_proj = (const float*)d_in[4];
    const float* b_proj = (const float*)d_in[5];
    const float* bias_table = (const float*)d_in[6];
    const float* alpha = (const float*)d_in[7];
    float* out = (float*)d_out;

    cudaFuncSetAttribute(attn2_kernel, cudaFuncAttributeMaxDynamicSharedMemorySize,
                         ATTN_SMEM_BYTES);
    cudaFuncSetAttribute(mma_gemm<true>, cudaFuncAttributeMaxDynamicSharedMemorySize,
                         GEMM_SMEM);
    cudaFuncSetAttribute(mma_gemm<false>, cudaFuncAttributeMaxDynamicSharedMemorySize,
                         GEMM_SMEM);

    split_a<<<3072, 256>>>(x);
    split_wt<<<dim3(ND3_ / 32, 24), dim3(32, 8)>>>(W_qkv, ND3_);
    mma_gemm<true><<<dim3(ND3_ / 128, 32), 256, GEMM_SMEM>>>(nullptr, nullptr);
    bidx_kernel<<<dim3(64, B_), 256>>>(coords);
    attn2_kernel<<<dim3(N_ / 128, H_, B_), 256, ATTN_SMEM_BYTES>>>(elev, bias_table, alpha);
    split_wt<<<dim3(D_ / 32, 24), dim3(32, 8)>>>(W_proj, D_);
    mma_gemm<false><<<dim3(D_ / 128, 32), 256, GEMM_SMEM>>>(b_proj, out);
}